// round 7
// baseline (speedup 1.0000x reference)
#include <cuda_runtime.h>

typedef unsigned long long u64;

// ---------------- problem constants ----------------
#define BB    64
#define MAXV  200
#define PP    40     // codes per visit
#define DOTH  57
#define KK    100
#define TT    8      // time steps per block (25 * 8 = 200 >= 198)
#define NTILE 25
#define TOUT  198
#define HID   256
#define RP    4      // rows per group in phase A (2 groups)

// Per-batch tgt contributions (time-invariant)
__device__ float g_tgtF[BB * HID];
__device__ float g_tgtB[BB * HID];

// ---------------- packed f32x2 helpers ----------------
__device__ __forceinline__ u64 f2fma(u64 a, u64 b, u64 c) {
    u64 d; asm("fma.rn.f32x2 %0,%1,%2,%3;" : "=l"(d) : "l"(a), "l"(b), "l"(c)); return d;
}
__device__ __forceinline__ u64 f2add(u64 a, u64 b) {
    u64 d; asm("add.rn.f32x2 %0,%1,%2;" : "=l"(d) : "l"(a), "l"(b)); return d;
}
__device__ __forceinline__ u64 dup2(float v) {
    u64 d; asm("mov.b64 %0,{%1,%1};" : "=l"(d) : "f"(v)); return d;
}
__device__ __forceinline__ void unpack2(u64 v, float& x, float& y) {
    asm("mov.b64 {%0,%1},%2;" : "=f"(x), "=f"(y) : "l"(v));
}
__device__ __forceinline__ u64 ldg2(const float* __restrict__ p) {
    return *reinterpret_cast<const u64*>(p);
}

// ---------------------------------------------------------------------------
// Kernel 1: per-batch tgt @ Wf[507:607] / Wb[507:607]
// ---------------------------------------------------------------------------
__global__ __launch_bounds__(256) void tgt_kernel(
    const int* __restrict__ target, const int* __restrict__ widx,
    const float* __restrict__ Wf, const float* __restrict__ Wb)
{
    __shared__ int s_t[10];
    __shared__ int s_keep[KK];
    const int b = blockIdx.x;
    const int j = threadIdx.x;
    if (j < 10) s_t[j] = target[b * 10 + j];
    __syncthreads();
    if (j < KK) {
        int w = widx[j];
        int keep = 1;
        #pragma unroll
        for (int q = 0; q < 10; q++) keep &= (s_t[q] != w);
        s_keep[j] = keep;
    }
    __syncthreads();
    float aF = 0.f, aB = 0.f;
    for (int k = 0; k < KK; k++) {
        if (s_keep[k]) {
            aF += Wf[(507 + k) * HID + j];
            aB += Wb[(507 + k) * HID + j];
        }
    }
    g_tgtF[b * HID + j] = aF;
    g_tgtB[b * HID + j] = aB;
}

// ---------------------------------------------------------------------------
// Dedup: multi_hot collapses duplicate codes within a row. -1 = skip.
// ---------------------------------------------------------------------------
__device__ __forceinline__ void dedup_codes(const int* __restrict__ s_codes,
                                            int* __restrict__ s_out, int j)
{
    for (int idx = j; idx < TT * PP; idx += 256) {
        int p = idx % PP;
        int base = idx - p;
        int c = s_codes[idx];
        int take = 1;
        for (int q = 0; q < p; q++) take &= (s_codes[base + q] != c);
        s_out[idx] = take ? c : -1;
    }
}

// ---------------------------------------------------------------------------
// Gather (sparse codes) + dense features, packed f32x2, RP rows per thread.
// Gather loads are UNCONDITIONAL (clamped index); only the add is predicated,
// so the LDG stream has no guard and batches deep.
// ---------------------------------------------------------------------------
__device__ __forceinline__ void gather_dense(
    u64* __restrict__ acc, const int* __restrict__ s_codes2,
    const u64* __restrict__ s_sc2, const float* __restrict__ W,
    int denseRow0, int nd, int g, int c0)
{
    #pragma unroll
    for (int lr = 0; lr < RP; lr++) {
        const int* cp = s_codes2 + (g * RP + lr) * PP;
        u64 a0 = acc[lr], a1 = 0ull;
        #pragma unroll 10
        for (int p = 0; p < PP; p += 2) {
            int ca = cp[p];
            int cb = cp[p + 1];
            u64 wa = ldg2(W + max(ca, 0) * HID + c0);
            u64 wb = ldg2(W + max(cb, 0) * HID + c0);
            if (ca >= 0) a0 = f2add(a0, wa);
            if (cb >= 0) a1 = f2add(a1, wb);
        }
        acc[lr] = f2add(a0, a1);
    }
    // dense part: pairs of feature columns, LDS.128 on duplicated scalars
    int i = 0;
    for (; i + 1 < nd; i += 2) {
        u64 w0 = ldg2(W + (denseRow0 + i) * HID + c0);
        u64 w1 = ldg2(W + (denseRow0 + i + 1) * HID + c0);
        #pragma unroll
        for (int lr = 0; lr < RP; lr++) {
            ulonglong2 s = *reinterpret_cast<const ulonglong2*>(&s_sc2[(g * RP + lr) * 64 + i]);
            acc[lr] = f2fma(s.x, w0, acc[lr]);
            acc[lr] = f2fma(s.y, w1, acc[lr]);
        }
    }
    if (i < nd) {
        u64 w0 = ldg2(W + (denseRow0 + i) * HID + c0);
        #pragma unroll
        for (int lr = 0; lr < RP; lr++)
            acc[lr] = f2fma(s_sc2[(g * RP + lr) * 64 + i], w0, acc[lr]);
    }
}

// ---------------------------------------------------------------------------
// Main kernel. Phase A (F/B/FV-layer0): 2 groups x RP rows, 128 col-pairs.
// Phase B (W1 GEMM): 128 col-pairs x 2 i-halves, all TT rows in registers.
// ---------------------------------------------------------------------------
__global__ __launch_bounds__(256, 6) void main_kernel(
    const int*   __restrict__ code,   const float* __restrict__ others,
    const int*   __restrict__ length,
    const float* __restrict__ Wf, const float* __restrict__ bf,
    const float* __restrict__ Wb, const float* __restrict__ bb,
    const float* __restrict__ W0, const float* __restrict__ b0,
    const float* __restrict__ W1, const float* __restrict__ b1,
    float* __restrict__ outF, float* __restrict__ outB, float* __restrict__ outV)
{
    // one aliased region: {codes(1280) | codes2(1280) | sc2(4096)}  ->
    //                     {h1 duplicated (16384)} -> {partials (8192)}
    __shared__ __align__(16) char s_mem[TT * HID * 8];
    __shared__ float s_red[4 * TT];
    __shared__ float s_rsq[TT];

    int* s_codes  = (int*)s_mem;
    int* s_codes2 = (int*)(s_mem + TT * PP * 4);
    u64* s_sc2    = (u64*)(s_mem + 2 * TT * PP * 4);
    u64* s_h1d    = (u64*)s_mem;
    u64* s_part   = (u64*)s_mem;

    const int b  = blockIdx.y;
    const int t0 = blockIdx.x * TT;
    const int j  = threadIdx.x;
    const int g  = j >> 7;        // group / i-half
    const int jc = j & 127;       // column pair id
    const int c0 = 2 * jc;
    const int L  = length[b];
    const float* oth = others + (size_t)b * MAXV * DOTH;
    const int*   cod = code   + (size_t)b * MAXV * PP;

    u64 acc[RP];

    // ============================ FORWARD ============================
    for (int idx = j; idx < TT * PP; idx += 256) {
        int r = idx / PP, p = idx - r * PP;
        s_codes[idx] = cod[(t0 + r) * PP + p];
    }
    for (int idx = j; idx < TT * 57; idx += 256) {
        int r = idx / 57, i = idx - r * 57;
        int col = (i < 27) ? i : ((i < 47) ? i + 10 : i - 20);
        s_sc2[r * 64 + i] = dup2(oth[(t0 + r) * DOTH + col]);
    }
    __syncthreads();
    dedup_codes(s_codes, s_codes2, j);
    __syncthreads();
    {
        u64 base = f2add(ldg2(bf + c0), ldg2(&g_tgtF[b * HID + c0]));
        #pragma unroll
        for (int lr = 0; lr < RP; lr++) acc[lr] = base;
    }
    gather_dense(acc, s_codes2, s_sc2, Wf, 607, 57, g, c0);
    #pragma unroll
    for (int lr = 0; lr < RP; lr++) {
        int t = t0 + g * RP + lr;
        if (t < TOUT)
            *reinterpret_cast<u64*>(&outF[((size_t)b * TOUT + t) * HID + c0]) = acc[lr];
    }

    // ============================ BACKWARD ============================
    __syncthreads();
    for (int idx = j; idx < TT * PP; idx += 256) {
        int r = idx / PP, p = idx - r * PP;
        int t = t0 + r;
        int rf = (t < L) ? (L - 1 - t) : t;
        s_codes[idx] = cod[rf * PP + p];
    }
    for (int idx = j; idx < TT * 57; idx += 256) {
        int r = idx / 57, i = idx - r * 57;
        int t = t0 + r;
        float v;
        if (i < 47) {
            int rf = (t < L) ? (L - 1 - t) : t;
            int col = (i < 27) ? i : i + 10;
            v = oth[rf * DOTH + col];
        } else {
            if (t == 0) v = 0.f;
            else {
                int ri = ((t - 1) < L) ? (L - t) : (t - 1);
                v = oth[ri * DOTH + (i - 20)];
            }
        }
        s_sc2[r * 64 + i] = dup2(v);
    }
    __syncthreads();
    dedup_codes(s_codes, s_codes2, j);
    __syncthreads();
    {
        u64 base = f2add(ldg2(bb + c0), ldg2(&g_tgtB[b * HID + c0]));
        #pragma unroll
        for (int lr = 0; lr < RP; lr++) acc[lr] = base;
    }
    gather_dense(acc, s_codes2, s_sc2, Wb, 607, 57, g, c0);
    #pragma unroll
    for (int lr = 0; lr < RP; lr++) {
        int t = t0 + g * RP + lr;
        if (t < TOUT)
            *reinterpret_cast<u64*>(&outB[((size_t)b * TOUT + t) * HID + c0]) = acc[lr];
    }

    // ============================ FV ============================
    __syncthreads();
    if (t0 < L - 2) {
        for (int idx = j; idx < TT * PP; idx += 256) {
            int r = idx / PP, p = idx - r * PP;
            int tv = min(t0 + r, TOUT - 1);
            s_codes[idx] = cod[(tv + 1) * PP + p];
        }
        for (int idx = j; idx < TT * 48; idx += 256) {
            int r = idx / 48, i = idx - r * 48;
            int tv = min(t0 + r, TOUT - 1);
            int row, col;
            if (i < 20)      { row = tv + 1; col = 37 + i; }
            else if (i < 30) { row = tv + 1; col = i + 7;  }
            else if (i < 40) { row = tv + 2; col = i - 3;  }
            else             { row = tv + 1; col = i - 21; }
            s_sc2[r * 64 + i] = dup2(oth[row * DOTH + col]);
        }
        __syncthreads();
        dedup_codes(s_codes, s_codes2, j);
        __syncthreads();
        {
            u64 base = ldg2(b0 + c0);
            #pragma unroll
            for (int lr = 0; lr < RP; lr++) acc[lr] = base;
        }
        gather_dense(acc, s_codes2, s_sc2, W0, 507, 48, g, c0);

        // relu -> duplicated h1 into the aliased region (after all reads done)
        __syncthreads();
        #pragma unroll
        for (int lr = 0; lr < RP; lr++) {
            float x, y; unpack2(acc[lr], x, y);
            int r = g * RP + lr;
            s_h1d[r * HID + c0]     = dup2(fmaxf(x, 0.f));
            s_h1d[r * HID + c0 + 1] = dup2(fmaxf(y, 0.f));
        }
        __syncthreads();

        // W1 GEMM: thread = (col-pair jc, i-half g); all TT rows in registers.
        u64 acc2[TT];
        {
            u64 init = (g == 0) ? ldg2(b1 + c0) : 0ull;
            #pragma unroll
            for (int r = 0; r < TT; r++) acc2[r] = init;
        }
        {
            const float* Wp = W1 + (size_t)(g * 128) * HID + c0;
            const u64*   hp = s_h1d + g * 128;
            for (int i = 0; i < 128; i += 2) {
                u64 w0 = ldg2(Wp + (size_t)i * HID);
                u64 w1 = ldg2(Wp + (size_t)(i + 1) * HID);
                #pragma unroll
                for (int r = 0; r < TT; r++) {
                    ulonglong2 hh = *reinterpret_cast<const ulonglong2*>(&hp[r * HID + i]);
                    acc2[r] = f2fma(hh.x, w0, acc2[r]);
                    acc2[r] = f2fma(hh.y, w1, acc2[r]);
                }
            }
        }
        // combine i-halves (deterministic order: half0 + half1)
        __syncthreads();     // all reads of s_h1d done before overwrite
        if (g == 1) {
            #pragma unroll
            for (int r = 0; r < TT; r++) s_part[r * 128 + jc] = acc2[r];
        }
        __syncthreads();
        if (g == 0) {
            #pragma unroll
            for (int r = 0; r < TT; r++) {
                acc2[r] = f2add(acc2[r], s_part[r * 128 + jc]);
                float x, y; unpack2(acc2[r], x, y);
                float v = x * x + y * y;
                v += __shfl_xor_sync(0xffffffffu, v, 16);
                v += __shfl_xor_sync(0xffffffffu, v, 8);
                v += __shfl_xor_sync(0xffffffffu, v, 4);
                v += __shfl_xor_sync(0xffffffffu, v, 2);
                v += __shfl_xor_sync(0xffffffffu, v, 1);
                if ((j & 31) == 0) s_red[(j >> 5) * TT + r] = v;
            }
        }
        __syncthreads();
        if (j < TT) {
            float s = 0.f;
            #pragma unroll
            for (int w = 0; w < 4; w++) s += s_red[w * TT + j];
            float inv = rsqrtf(s);
            inv = inv * (1.5f - 0.5f * s * inv * inv);  // Newton step
            s_rsq[j] = inv;
        }
        __syncthreads();
        if (g == 0) {
            #pragma unroll
            for (int r = 0; r < TT; r++) {
                int t = t0 + r;
                if (t < TOUT) {
                    float m = (t < L - 2) ? s_rsq[r] : 0.f;
                    float x, y; unpack2(acc2[r], x, y);
                    float2 o = make_float2(x * m, y * m);
                    *reinterpret_cast<float2*>(&outV[((size_t)b * TOUT + t) * HID + c0]) = o;
                }
            }
        }
    } else {
        // fully masked tile: fv rows exactly zero
        #pragma unroll
        for (int lr = 0; lr < RP; lr++) {
            int t = t0 + g * RP + lr;
            if (t < TOUT)
                *reinterpret_cast<u64*>(&outV[((size_t)b * TOUT + t) * HID + c0]) = 0ull;
        }
    }
}

// ---------------------------------------------------------------------------
extern "C" void kernel_launch(void* const* d_in, const int* in_sizes, int n_in,
                              void* d_out, int out_size)
{
    (void)in_sizes; (void)n_in; (void)out_size;
    const int*   code    = (const int*)  d_in[0];
    const float* others  = (const float*)d_in[1];
    const int*   length  = (const int*)  d_in[2];
    const int*   target  = (const int*)  d_in[3];
    const int*   widx    = (const int*)  d_in[4];
    const float* Wf      = (const float*)d_in[5];
    const float* bf      = (const float*)d_in[6];
    const float* Wb      = (const float*)d_in[7];
    const float* bb      = (const float*)d_in[8];
    const float* W0      = (const float*)d_in[9];
    const float* b0      = (const float*)d_in[10];
    const float* W1      = (const float*)d_in[11];
    const float* b1      = (const float*)d_in[12];

    float* outF = (float*)d_out;
    float* outB = outF + (size_t)BB * TOUT * HID;
    float* outV = outB + (size_t)BB * TOUT * HID;

    tgt_kernel<<<BB, 256>>>(target, widx, Wf, Wb);
    main_kernel<<<dim3(NTILE, BB), 256>>>(code, others, length,
                                          Wf, bf, Wb, bb, W0, b0, W1, b1,
                                          outF, outB, outV);
}

// round 10
// speedup vs baseline: 1.5725x; 1.5725x over previous
#include <cuda_runtime.h>

typedef unsigned long long u64;

// ---------------- problem constants ----------------
#define BB    64
#define MAXV  200
#define PP    40     // codes per visit
#define DOTH  57
#define KK    100
#define TT    10     // time steps per block (20 * 10 = 200 >= 198)
#define NTILE 20
#define TOUT  198
#define HID   256

// Per-batch tgt contributions (time-invariant)
__device__ float g_tgtF[BB * HID];
__device__ float g_tgtB[BB * HID];

// ---------------- packed f32x2 helpers ----------------
__device__ __forceinline__ u64 f2fma(u64 a, u64 b, u64 c) {
    u64 d; asm("fma.rn.f32x2 %0,%1,%2,%3;" : "=l"(d) : "l"(a), "l"(b), "l"(c)); return d;
}
__device__ __forceinline__ u64 f2add(u64 a, u64 b) {
    u64 d; asm("add.rn.f32x2 %0,%1,%2;" : "=l"(d) : "l"(a), "l"(b)); return d;
}
__device__ __forceinline__ u64 dup2(float v) {
    u64 d; asm("mov.b64 %0,{%1,%1};" : "=l"(d) : "f"(v)); return d;
}
__device__ __forceinline__ void unpack2(u64 v, float& x, float& y) {
    asm("mov.b64 {%0,%1},%2;" : "=f"(x), "=f"(y) : "l"(v));
}
__device__ __forceinline__ u64 ldg2(const float* __restrict__ p) {
    return *reinterpret_cast<const u64*>(p);
}
__device__ __forceinline__ ulonglong2 ldg4(const float* __restrict__ p) {
    return *reinterpret_cast<const ulonglong2*>(p);
}

// ---------------------------------------------------------------------------
// Kernel 1: per-batch tgt @ Wf[507:607] / Wb[507:607]
// ---------------------------------------------------------------------------
__global__ __launch_bounds__(256) void tgt_kernel(
    const int* __restrict__ target, const int* __restrict__ widx,
    const float* __restrict__ Wf, const float* __restrict__ Wb)
{
    __shared__ int s_t[10];
    __shared__ int s_keep[KK];
    const int b = blockIdx.x;
    const int j = threadIdx.x;
    if (j < 10) s_t[j] = target[b * 10 + j];
    __syncthreads();
    if (j < KK) {
        int w = widx[j];
        int keep = 1;
        #pragma unroll
        for (int q = 0; q < 10; q++) keep &= (s_t[q] != w);
        s_keep[j] = keep;
    }
    __syncthreads();
    float aF = 0.f, aB = 0.f;
    for (int k = 0; k < KK; k++) {
        if (s_keep[k]) {
            aF += Wf[(507 + k) * HID + j];
            aB += Wb[(507 + k) * HID + j];
        }
    }
    g_tgtF[b * HID + j] = aF;
    g_tgtB[b * HID + j] = aB;
}

// ---------------------------------------------------------------------------
// Dedup: multi_hot collapses duplicate codes within a row. -1 = skip.
// ---------------------------------------------------------------------------
__device__ __forceinline__ void dedup_codes(const int* __restrict__ s_codes,
                                            int* __restrict__ s_out, int j)
{
    for (int idx = j; idx < TT * PP; idx += 256) {
        int p = idx % PP;
        int base = idx - p;
        int c = s_codes[idx];
        int take = 1;
        for (int q = 0; q < p; q++) take &= (s_codes[base + q] != c);
        s_out[idx] = take ? c : -1;
    }
}

// ---------------------------------------------------------------------------
// Phase-A gather+dense, 4 output columns per thread (LDG.128), up to 3 rows.
// acc[lr][0] = packed cols (c0,c0+1), acc[lr][1] = (c0+2,c0+3).
// ---------------------------------------------------------------------------
__device__ __forceinline__ void gather_dense4(
    u64 (* __restrict__ acc)[2], const int* __restrict__ s_codes2,
    const u64* __restrict__ s_sc2, const float* __restrict__ W,
    int denseRow0, int nd, int rbase, int nr, int c0)
{
    // sparse gathers: int4 code reads, unconditional clamped LDG.128,
    // predicated packed adds; two accumulator pairs for ILP
    #pragma unroll
    for (int lr = 0; lr < 3; lr++) {
        if (lr < nr) {
            const int4* cp = (const int4*)(s_codes2 + (rbase + lr) * PP);
            u64 a0 = acc[lr][0], a1 = acc[lr][1];
            u64 d0 = 0ull, d1 = 0ull;
            #pragma unroll
            for (int p4 = 0; p4 < PP / 4; p4++) {
                int4 c = cp[p4];
                ulonglong2 w0 = ldg4(W + max(c.x, 0) * HID + c0);
                ulonglong2 w1 = ldg4(W + max(c.y, 0) * HID + c0);
                ulonglong2 w2 = ldg4(W + max(c.z, 0) * HID + c0);
                ulonglong2 w3 = ldg4(W + max(c.w, 0) * HID + c0);
                if (c.x >= 0) { a0 = f2add(a0, w0.x); a1 = f2add(a1, w0.y); }
                if (c.y >= 0) { d0 = f2add(d0, w1.x); d1 = f2add(d1, w1.y); }
                if (c.z >= 0) { a0 = f2add(a0, w2.x); a1 = f2add(a1, w2.y); }
                if (c.w >= 0) { d0 = f2add(d0, w3.x); d1 = f2add(d1, w3.y); }
            }
            acc[lr][0] = f2add(a0, d0);
            acc[lr][1] = f2add(a1, d1);
        }
    }
    // dense features: 2 feature rows per iter, LDS.128 of duplicated scalars
    int i = 0;
    for (; i + 1 < nd; i += 2) {
        ulonglong2 wA = ldg4(W + (denseRow0 + i) * HID + c0);
        ulonglong2 wB = ldg4(W + (denseRow0 + i + 1) * HID + c0);
        #pragma unroll
        for (int lr = 0; lr < 3; lr++) {
            if (lr < nr) {
                ulonglong2 s = *reinterpret_cast<const ulonglong2*>(
                    &s_sc2[(rbase + lr) * 64 + i]);
                acc[lr][0] = f2fma(s.x, wA.x, acc[lr][0]);
                acc[lr][1] = f2fma(s.x, wA.y, acc[lr][1]);
                acc[lr][0] = f2fma(s.y, wB.x, acc[lr][0]);
                acc[lr][1] = f2fma(s.y, wB.y, acc[lr][1]);
            }
        }
    }
    if (i < nd) {
        ulonglong2 wA = ldg4(W + (denseRow0 + i) * HID + c0);
        #pragma unroll
        for (int lr = 0; lr < 3; lr++) {
            if (lr < nr) {
                u64 s = s_sc2[(rbase + lr) * 64 + i];
                acc[lr][0] = f2fma(s, wA.x, acc[lr][0]);
                acc[lr][1] = f2fma(s, wA.y, acc[lr][1]);
            }
        }
    }
}

// ---------------------------------------------------------------------------
// Main kernel.
// Phase A (F/B/FV-layer0): 64 col-quads x 4 row-groups (rows {3,3,2,2}).
// Phase B (W1 GEMM): 128 col-pairs x 2 i-halves, all TT rows in registers.
// ---------------------------------------------------------------------------
__global__ __launch_bounds__(256, 5) void main_kernel(
    const int*   __restrict__ code,   const float* __restrict__ others,
    const int*   __restrict__ length,
    const float* __restrict__ Wf, const float* __restrict__ bf,
    const float* __restrict__ Wb, const float* __restrict__ bb,
    const float* __restrict__ W0, const float* __restrict__ b0,
    const float* __restrict__ W1, const float* __restrict__ b1,
    float* __restrict__ outF, float* __restrict__ outB, float* __restrict__ outV)
{
    // aliased region: {codes(1600) | codes2(1600) | sc2(5120)} ->
    //                 {h1 duplicated (20480)} -> {partials (10240)}
    __shared__ __align__(16) char s_mem[TT * HID * 8];
    __shared__ float s_red[4 * TT];
    __shared__ float s_rsq[TT];

    int* s_codes  = (int*)s_mem;
    int* s_codes2 = (int*)(s_mem + TT * PP * 4);
    u64* s_sc2    = (u64*)(s_mem + 2 * TT * PP * 4);
    u64* s_h1d    = (u64*)s_mem;
    u64* s_part   = (u64*)s_mem;

    const int b  = blockIdx.y;
    const int t0 = blockIdx.x * TT;
    const int j  = threadIdx.x;
    // phase-A mapping: 64 col-quads x 4 row-groups (warp-uniform g)
    const int q  = j & 63;
    const int g  = j >> 6;
    const int c0 = q * 4;
    const int rbase = (g < 2) ? g * 3 : 2 + g * 2;   // 0,3,6,8
    const int nr    = (g < 2) ? 3 : 2;
    // phase-B mapping
    const int g2 = j >> 7;
    const int jc = j & 127;
    const int c2 = 2 * jc;

    const int L  = length[b];
    const float* oth = others + (size_t)b * MAXV * DOTH;
    const int*   cod = code   + (size_t)b * MAXV * PP;

    u64 acc[3][2];

    // ============================ FORWARD ============================
    for (int idx = j; idx < TT * PP; idx += 256) {
        int r = idx / PP, p = idx - r * PP;
        s_codes[idx] = cod[(t0 + r) * PP + p];
    }
    for (int idx = j; idx < TT * 57; idx += 256) {
        int r = idx / 57, i = idx - r * 57;
        int col = (i < 27) ? i : ((i < 47) ? i + 10 : i - 20);
        s_sc2[r * 64 + i] = dup2(oth[(t0 + r) * DOTH + col]);
    }
    __syncthreads();
    dedup_codes(s_codes, s_codes2, j);
    __syncthreads();
    {
        ulonglong2 bv = ldg4(bf + c0);
        ulonglong2 tv = ldg4(&g_tgtF[b * HID + c0]);
        u64 base0 = f2add(bv.x, tv.x), base1 = f2add(bv.y, tv.y);
        #pragma unroll
        for (int lr = 0; lr < 3; lr++) { acc[lr][0] = base0; acc[lr][1] = base1; }
    }
    gather_dense4(acc, s_codes2, s_sc2, Wf, 607, 57, rbase, nr, c0);
    #pragma unroll
    for (int lr = 0; lr < 3; lr++) {
        int t = t0 + rbase + lr;
        if (lr < nr && t < TOUT) {
            ulonglong2 v; v.x = acc[lr][0]; v.y = acc[lr][1];
            *reinterpret_cast<ulonglong2*>(&outF[((size_t)b * TOUT + t) * HID + c0]) = v;
        }
    }

    // ============================ BACKWARD ============================
    __syncthreads();
    for (int idx = j; idx < TT * PP; idx += 256) {
        int r = idx / PP, p = idx - r * PP;
        int t = t0 + r;
        int rf = (t < L) ? (L - 1 - t) : t;
        s_codes[idx] = cod[rf * PP + p];
    }
    for (int idx = j; idx < TT * 57; idx += 256) {
        int r = idx / 57, i = idx - r * 57;
        int t = t0 + r;
        float v;
        if (i < 47) {
            int rf = (t < L) ? (L - 1 - t) : t;
            int col = (i < 27) ? i : i + 10;
            v = oth[rf * DOTH + col];
        } else {
            if (t == 0) v = 0.f;
            else {
                int ri = ((t - 1) < L) ? (L - t) : (t - 1);
                v = oth[ri * DOTH + (i - 20)];
            }
        }
        s_sc2[r * 64 + i] = dup2(v);
    }
    __syncthreads();
    dedup_codes(s_codes, s_codes2, j);
    __syncthreads();
    {
        ulonglong2 bv = ldg4(bb + c0);
        ulonglong2 tv = ldg4(&g_tgtB[b * HID + c0]);
        u64 base0 = f2add(bv.x, tv.x), base1 = f2add(bv.y, tv.y);
        #pragma unroll
        for (int lr = 0; lr < 3; lr++) { acc[lr][0] = base0; acc[lr][1] = base1; }
    }
    gather_dense4(acc, s_codes2, s_sc2, Wb, 607, 57, rbase, nr, c0);
    #pragma unroll
    for (int lr = 0; lr < 3; lr++) {
        int t = t0 + rbase + lr;
        if (lr < nr && t < TOUT) {
            ulonglong2 v; v.x = acc[lr][0]; v.y = acc[lr][1];
            *reinterpret_cast<ulonglong2*>(&outB[((size_t)b * TOUT + t) * HID + c0]) = v;
        }
    }

    // ============================ FV ============================
    __syncthreads();
    if (t0 < L - 2) {
        for (int idx = j; idx < TT * PP; idx += 256) {
            int r = idx / PP, p = idx - r * PP;
            int tv = min(t0 + r, TOUT - 1);
            s_codes[idx] = cod[(tv + 1) * PP + p];
        }
        for (int idx = j; idx < TT * 48; idx += 256) {
            int r = idx / 48, i = idx - r * 48;
            int tv = min(t0 + r, TOUT - 1);
            int row, col;
            if (i < 20)      { row = tv + 1; col = 37 + i; }
            else if (i < 30) { row = tv + 1; col = i + 7;  }
            else if (i < 40) { row = tv + 2; col = i - 3;  }
            else             { row = tv + 1; col = i - 21; }
            s_sc2[r * 64 + i] = dup2(oth[row * DOTH + col]);
        }
        __syncthreads();
        dedup_codes(s_codes, s_codes2, j);
        __syncthreads();
        {
            ulonglong2 bv = ldg4(b0 + c0);
            #pragma unroll
            for (int lr = 0; lr < 3; lr++) { acc[lr][0] = bv.x; acc[lr][1] = bv.y; }
        }
        gather_dense4(acc, s_codes2, s_sc2, W0, 507, 48, rbase, nr, c0);

        // relu -> duplicated h1 into the aliased region (after all reads done)
        __syncthreads();
        #pragma unroll
        for (int lr = 0; lr < 3; lr++) {
            if (lr < nr) {
                int r = rbase + lr;
                float x0, x1, x2, x3;
                unpack2(acc[lr][0], x0, x1);
                unpack2(acc[lr][1], x2, x3);
                ulonglong2 v0; v0.x = dup2(fmaxf(x0, 0.f)); v0.y = dup2(fmaxf(x1, 0.f));
                ulonglong2 v1; v1.x = dup2(fmaxf(x2, 0.f)); v1.y = dup2(fmaxf(x3, 0.f));
                *reinterpret_cast<ulonglong2*>(&s_h1d[r * HID + c0])     = v0;
                *reinterpret_cast<ulonglong2*>(&s_h1d[r * HID + c0 + 2]) = v1;
            }
        }
        __syncthreads();

        // W1 GEMM: thread = (col-pair jc, i-half g2); all TT rows in registers.
        u64 acc2[TT];
        {
            u64 init = (g2 == 0) ? ldg2(b1 + c2) : 0ull;
            #pragma unroll
            for (int r = 0; r < TT; r++) acc2[r] = init;
        }
        {
            const float* Wp = W1 + (size_t)(g2 * 128) * HID + c2;
            const u64*   hp = s_h1d + g2 * 128;
            for (int i = 0; i < 128; i += 2) {
                u64 w0 = ldg2(Wp + (size_t)i * HID);
                u64 w1 = ldg2(Wp + (size_t)(i + 1) * HID);
                #pragma unroll
                for (int r = 0; r < TT; r++) {
                    ulonglong2 hh = *reinterpret_cast<const ulonglong2*>(&hp[r * HID + i]);
                    acc2[r] = f2fma(hh.x, w0, acc2[r]);
                    acc2[r] = f2fma(hh.y, w1, acc2[r]);
                }
            }
        }
        // combine i-halves (deterministic order: half0 + half1)
        __syncthreads();     // all reads of s_h1d done before overwrite
        if (g2 == 1) {
            #pragma unroll
            for (int r = 0; r < TT; r++) s_part[r * 128 + jc] = acc2[r];
        }
        __syncthreads();
        if (g2 == 0) {
            #pragma unroll
            for (int r = 0; r < TT; r++) {
                acc2[r] = f2add(acc2[r], s_part[r * 128 + jc]);
                float x, y; unpack2(acc2[r], x, y);
                float v = x * x + y * y;
                v += __shfl_xor_sync(0xffffffffu, v, 16);
                v += __shfl_xor_sync(0xffffffffu, v, 8);
                v += __shfl_xor_sync(0xffffffffu, v, 4);
                v += __shfl_xor_sync(0xffffffffu, v, 2);
                v += __shfl_xor_sync(0xffffffffu, v, 1);
                if ((j & 31) == 0) s_red[(j >> 5) * TT + r] = v;
            }
        }
        __syncthreads();
        if (j < TT) {
            float s = 0.f;
            #pragma unroll
            for (int w = 0; w < 4; w++) s += s_red[w * TT + j];
            float inv = rsqrtf(s);
            inv = inv * (1.5f - 0.5f * s * inv * inv);  // Newton step
            s_rsq[j] = inv;
        }
        __syncthreads();
        if (g2 == 0) {
            #pragma unroll
            for (int r = 0; r < TT; r++) {
                int t = t0 + r;
                if (t < TOUT) {
                    float m = (t < L - 2) ? s_rsq[r] : 0.f;
                    float x, y; unpack2(acc2[r], x, y);
                    float2 o = make_float2(x * m, y * m);
                    *reinterpret_cast<float2*>(&outV[((size_t)b * TOUT + t) * HID + c2]) = o;
                }
            }
        }
    } else {
        // fully masked tile: fv rows exactly zero
        #pragma unroll
        for (int lr = 0; lr < 3; lr++) {
            int t = t0 + rbase + lr;
            if (lr < nr && t < TOUT) {
                ulonglong2 z; z.x = 0ull; z.y = 0ull;
                *reinterpret_cast<ulonglong2*>(&outV[((size_t)b * TOUT + t) * HID + c0]) = z;
            }
        }
    }
}

// ---------------------------------------------------------------------------
extern "C" void kernel_launch(void* const* d_in, const int* in_sizes, int n_in,
                              void* d_out, int out_size)
{
    (void)in_sizes; (void)n_in; (void)out_size;
    const int*   code    = (const int*)  d_in[0];
    const float* others  = (const float*)d_in[1];
    const int*   length  = (const int*)  d_in[2];
    const int*   target  = (const int*)  d_in[3];
    const int*   widx    = (const int*)  d_in[4];
    const float* Wf      = (const float*)d_in[5];
    const float* bf      = (const float*)d_in[6];
    const float* Wb      = (const float*)d_in[7];
    const float* bb      = (const float*)d_in[8];
    const float* W0      = (const float*)d_in[9];
    const float* b0      = (const float*)d_in[10];
    const float* W1      = (const float*)d_in[11];
    const float* b1      = (const float*)d_in[12];

    float* outF = (float*)d_out;
    float* outB = outF + (size_t)BB * TOUT * HID;
    float* outV = outB + (size_t)BB * TOUT * HID;

    tgt_kernel<<<BB, 256>>>(target, widx, Wf, Wb);
    main_kernel<<<dim3(NTILE, BB), 256>>>(code, others, length,
                                          Wf, bf, Wb, bb, W0, b0, W1, b1,
                                          outF, outB, outV);
}

// round 12
// speedup vs baseline: 1.7371x; 1.1046x over previous
#include <cuda_runtime.h>

typedef unsigned long long u64;

// ---------------- problem constants ----------------
#define BB    64
#define MAXV  200
#define PP    40
#define DOTH  57
#define KK    100
#define TTA   8      // rows per block in kernel A (25 * 8 = 200 rows)
#define NTA   25
#define TTC   10     // t-steps per block in kernel C (20 * 10 = 200 >= 198)
#define NTC   20
#define TOUT  198
#define HID   256

// Per-batch tgt contributions (time-invariant)
__device__ float g_tgtF[BB * HID];
__device__ float g_tgtB[BB * HID];
// h1 scratch (duplicated f32x2 format), 200 t-rows for guard-free access: ~26 MB
__device__ u64 g_h1d[(size_t)BB * MAXV * HID];

// ---------------- packed f32x2 helpers ----------------
__device__ __forceinline__ u64 f2fma(u64 a, u64 b, u64 c) {
    u64 d; asm("fma.rn.f32x2 %0,%1,%2,%3;" : "=l"(d) : "l"(a), "l"(b), "l"(c)); return d;
}
__device__ __forceinline__ u64 f2add(u64 a, u64 b) {
    u64 d; asm("add.rn.f32x2 %0,%1,%2;" : "=l"(d) : "l"(a), "l"(b)); return d;
}
__device__ __forceinline__ u64 dup2(float v) {
    u64 d; asm("mov.b64 %0,{%1,%1};" : "=l"(d) : "f"(v)); return d;
}
__device__ __forceinline__ void unpack2(u64 v, float& x, float& y) {
    asm("mov.b64 {%0,%1},%2;" : "=f"(x), "=f"(y) : "l"(v));
}
__device__ __forceinline__ u64 ldg2(const float* __restrict__ p) {
    return *reinterpret_cast<const u64*>(p);
}

// ---------------------------------------------------------------------------
// Kernel 1: per-batch tgt @ Wf[507:607] / Wb[507:607]
// ---------------------------------------------------------------------------
__global__ __launch_bounds__(256) void tgt_kernel(
    const int* __restrict__ target, const int* __restrict__ widx,
    const float* __restrict__ Wf, const float* __restrict__ Wb)
{
    __shared__ int s_t[10];
    __shared__ int s_keep[KK];
    const int b = blockIdx.x;
    const int j = threadIdx.x;
    if (j < 10) s_t[j] = target[b * 10 + j];
    __syncthreads();
    if (j < KK) {
        int w = widx[j];
        int keep = 1;
        #pragma unroll
        for (int q = 0; q < 10; q++) keep &= (s_t[q] != w);
        s_keep[j] = keep;
    }
    __syncthreads();
    float aF = 0.f, aB = 0.f;
    for (int k = 0; k < KK; k++) {
        if (s_keep[k]) {
            aF += Wf[(507 + k) * HID + j];
            aB += Wb[(507 + k) * HID + j];
        }
    }
    g_tgtF[b * HID + j] = aF;
    g_tgtB[b * HID + j] = aB;
}

// ---------------------------------------------------------------------------
// Dedup within each row of PP codes (multi_hot duplicate collapse). -1 = skip.
// ---------------------------------------------------------------------------
__device__ __forceinline__ void dedup_codes(const int* __restrict__ s_codes,
                                            int* __restrict__ s_out, int j)
{
    for (int idx = j; idx < TTA * PP; idx += 256) {
        int p = idx % PP;
        int base = idx - p;
        int c = s_codes[idx];
        int take = 1;
        for (int q = 0; q < p; q++) take &= (s_codes[base + q] != c);
        s_out[idx] = take ? c : -1;
    }
}

// ---------------------------------------------------------------------------
// Dense feature accumulate: 4 rows, f32x2-packed, ull2 scalar pair reads.
// ---------------------------------------------------------------------------
__device__ __forceinline__ void dense_acc(
    u64* __restrict__ acc, const u64* __restrict__ sc, int stride, int nd,
    const float* __restrict__ W, int row0, int rbase, int c0)
{
    int i = 0;
    for (; i + 1 < nd; i += 2) {
        u64 w0 = ldg2(W + (size_t)(row0 + i) * HID + c0);
        u64 w1 = ldg2(W + (size_t)(row0 + i + 1) * HID + c0);
        #pragma unroll
        for (int lr = 0; lr < 4; lr++) {
            ulonglong2 s = *reinterpret_cast<const ulonglong2*>(&sc[(rbase + lr) * stride + i]);
            acc[lr] = f2fma(s.x, w0, acc[lr]);
            acc[lr] = f2fma(s.y, w1, acc[lr]);
        }
    }
    if (i < nd) {
        u64 w0 = ldg2(W + (size_t)(row0 + i) * HID + c0);
        #pragma unroll
        for (int lr = 0; lr < 4; lr++)
            acc[lr] = f2fma(sc[(rbase + lr) * stride + i], w0, acc[lr]);
    }
}

// ---------------------------------------------------------------------------
// Kernel A: unified per-row gathers. Block = (b, 8 rows v). One code stage +
// one dedup drives Wf/Wb/W0 gathers simultaneously (3x MLP, 1/3 code LDS).
// outF[t=v], outB scattered to t_b(v), h1(relu) -> global scratch at t=v-1.
// ---------------------------------------------------------------------------
__global__ __launch_bounds__(256, 5) void kernelA(
    const int*   __restrict__ code,   const float* __restrict__ others,
    const int*   __restrict__ length,
    const float* __restrict__ Wf, const float* __restrict__ bf,
    const float* __restrict__ Wb, const float* __restrict__ bb,
    const float* __restrict__ W0, const float* __restrict__ b0,
    float* __restrict__ outF, float* __restrict__ outB)
{
    __shared__ int s_codes[TTA * PP];
    __shared__ int s_codes2[TTA * PP];
    __shared__ __align__(16) u64 s_scF[TTA * 58];
    __shared__ __align__(16) u64 s_scB[TTA * 58];
    __shared__ __align__(16) u64 s_scV[TTA * 48];

    const int b  = blockIdx.y;
    const int v0 = blockIdx.x * TTA;
    const int j  = threadIdx.x;
    const int jc = j & 127;
    const int g  = j >> 7;
    const int c0 = 2 * jc;
    const int rbase = g * 4;
    const int L  = length[b];
    const bool fvA = (v0 <= L - 2);   // any row v in block has v <= L-2

    const float* oth = others + (size_t)b * MAXV * DOTH;
    const int*   cod = code   + (size_t)b * MAXV * PP;

    // ---- stage codes ----
    for (int idx = j; idx < TTA * PP; idx += 256) {
        int r = idx / PP, p = idx - r * PP;
        s_codes[idx] = cod[(v0 + r) * PP + p];
    }
    // ---- stage forward scalars (57) ----
    for (int idx = j; idx < TTA * 57; idx += 256) {
        int r = idx / 57, i = idx - r * 57;
        int col = (i < 27) ? i : ((i < 47) ? i + 10 : i - 20);
        s_scF[r * 58 + i] = dup2(oth[(v0 + r) * DOTH + col]);
    }
    // ---- stage backward scalars (57): cols 0..46 = feature(v), 47..56 = interval(w(v)) ----
    for (int idx = j; idx < TTA * 57; idx += 256) {
        int r = idx / 57, i = idx - r * 57;
        int v = v0 + r;
        float val;
        if (i < 47) {
            int col = (i < 27) ? i : i + 10;
            val = oth[v * DOTH + col];
        } else {
            if (v == L - 1) val = 0.f;
            else {
                int w = (v <= L - 2) ? (v + 1) : ((v == L) ? 0 : (v - 1));
                val = oth[w * DOTH + 27 + (i - 47)];
            }
        }
        s_scB[r * 58 + i] = dup2(val);
    }
    // ---- stage FV scalars (48) for output t = v-1 ----
    if (fvA) {
        for (int idx = j; idx < TTA * 48; idx += 256) {
            int r = idx / 48, i = idx - r * 48;
            int v = v0 + r;
            float val;
            if (i < 20)      val = oth[v * DOTH + 37 + i];
            else if (i < 30) val = oth[v * DOTH + 7 + i];         // 27 + (i-20)
            else if (i < 40) val = (v + 1 < MAXV) ? oth[(v + 1) * DOTH + (i - 3)] : 0.f; // 27+(i-30)
            else             val = oth[v * DOTH + (i - 21)];      // 19 + (i-40)
            s_scV[r * 48 + i] = dup2(val);
        }
    }
    __syncthreads();
    dedup_codes(s_codes, s_codes2, j);
    __syncthreads();

    u64 aF[4], aB[4], a0[4];
    {
        u64 baseF = f2add(ldg2(bf + c0), ldg2(&g_tgtF[b * HID + c0]));
        u64 baseB = f2add(ldg2(bb + c0), ldg2(&g_tgtB[b * HID + c0]));
        u64 base0 = fvA ? ldg2(b0 + c0) : 0ull;
        #pragma unroll
        for (int lr = 0; lr < 4; lr++) { aF[lr] = baseF; aB[lr] = baseB; a0[lr] = base0; }
    }

    // ---- merged gathers: one code read drives 3 (or 2) weight loads ----
    if (fvA) {
        #pragma unroll
        for (int lr = 0; lr < 4; lr++) {
            const int* cp = s_codes2 + (rbase + lr) * PP;
            u64 f = aF[lr], bk = aB[lr], z = a0[lr];
            #pragma unroll 4
            for (int p = 0; p < PP; p++) {
                int c = cp[p];
                int cc = max(c, 0);
                u64 wf = ldg2(Wf + (size_t)cc * HID + c0);
                u64 wb = ldg2(Wb + (size_t)cc * HID + c0);
                u64 w0 = ldg2(W0 + (size_t)cc * HID + c0);
                if (c >= 0) { f = f2add(f, wf); bk = f2add(bk, wb); z = f2add(z, w0); }
            }
            aF[lr] = f; aB[lr] = bk; a0[lr] = z;
        }
    } else {
        #pragma unroll
        for (int lr = 0; lr < 4; lr++) {
            const int* cp = s_codes2 + (rbase + lr) * PP;
            u64 f = aF[lr], bk = aB[lr];
            #pragma unroll 4
            for (int p = 0; p < PP; p++) {
                int c = cp[p];
                int cc = max(c, 0);
                u64 wf = ldg2(Wf + (size_t)cc * HID + c0);
                u64 wb = ldg2(Wb + (size_t)cc * HID + c0);
                if (c >= 0) { f = f2add(f, wf); bk = f2add(bk, wb); }
            }
            aF[lr] = f; aB[lr] = bk;
        }
    }

    // ---- dense parts ----
    dense_acc(aF, s_scF, 58, 57, Wf, 607, rbase, c0);
    dense_acc(aB, s_scB, 58, 57, Wb, 607, rbase, c0);
    if (fvA) dense_acc(a0, s_scV, 48, 48, W0, 507, rbase, c0);

    // ---- stores ----
    #pragma unroll
    for (int lr = 0; lr < 4; lr++) {
        int v = v0 + rbase + lr;
        if (v < TOUT)
            *reinterpret_cast<u64*>(&outF[((size_t)b * TOUT + v) * HID + c0]) = aF[lr];
        int tb = (v < L) ? (L - 1 - v) : v;
        if (tb < TOUT)
            *reinterpret_cast<u64*>(&outB[((size_t)b * TOUT + tb) * HID + c0]) = aB[lr];
        if (fvA && v >= 1) {
            float x, y; unpack2(a0[lr], x, y);
            ulonglong2 hv;
            hv.x = dup2(fmaxf(x, 0.f));
            hv.y = dup2(fmaxf(y, 0.f));
            *reinterpret_cast<ulonglong2*>(&g_h1d[((size_t)b * MAXV + (v - 1)) * HID + c0]) = hv;
        }
    }
}

// ---------------------------------------------------------------------------
// Kernel C: W1 GEMM + L2 norm over t-tiles, reading h1 scratch.
// 128 col-pairs x 2 i-halves, all TTC rows register-resident.
// ---------------------------------------------------------------------------
__global__ __launch_bounds__(256, 5) void kernelC(
    const int* __restrict__ length,
    const float* __restrict__ W1, const float* __restrict__ b1,
    float* __restrict__ outV)
{
    __shared__ __align__(16) u64 s_h1d[TTC * HID];   // 20 KB; re-used as s_part
    __shared__ float s_red[4 * TTC];
    __shared__ float s_rsq[TTC];

    const int b  = blockIdx.y;
    const int t0 = blockIdx.x * TTC;
    const int j  = threadIdx.x;
    const int g2 = j >> 7;
    const int jc = j & 127;
    const int c2 = 2 * jc;
    const int L  = length[b];

    if (t0 < L - 2) {
        // load h1 tile (duplicated format) from scratch
        {
            const ulonglong2* src = reinterpret_cast<const ulonglong2*>(
                &g_h1d[((size_t)b * MAXV + t0) * HID]);
            ulonglong2* dst = reinterpret_cast<ulonglong2*>(s_h1d);
            #pragma unroll
            for (int k = 0; k < (TTC * HID / 2) / 256; k++)
                dst[j + k * 256] = src[j + k * 256];
        }
        __syncthreads();

        u64 acc2[TTC];
        {
            u64 init = (g2 == 0) ? ldg2(b1 + c2) : 0ull;
            #pragma unroll
            for (int r = 0; r < TTC; r++) acc2[r] = init;
        }
        {
            const float* Wp = W1 + (size_t)(g2 * 128) * HID + c2;
            const u64*   hp = s_h1d + g2 * 128;
            for (int i = 0; i < 128; i += 2) {
                u64 w0 = ldg2(Wp + (size_t)i * HID);
                u64 w1 = ldg2(Wp + (size_t)(i + 1) * HID);
                #pragma unroll
                for (int r = 0; r < TTC; r++) {
                    ulonglong2 hh = *reinterpret_cast<const ulonglong2*>(&hp[r * HID + i]);
                    acc2[r] = f2fma(hh.x, w0, acc2[r]);
                    acc2[r] = f2fma(hh.y, w1, acc2[r]);
                }
            }
        }
        __syncthreads();   // all reads of s_h1d done before aliasing as s_part
        u64* s_part = s_h1d;
        if (g2 == 1) {
            #pragma unroll
            for (int r = 0; r < TTC; r++) s_part[r * 128 + jc] = acc2[r];
        }
        __syncthreads();
        if (g2 == 0) {
            #pragma unroll
            for (int r = 0; r < TTC; r++) {
                acc2[r] = f2add(acc2[r], s_part[r * 128 + jc]);
                float x, y; unpack2(acc2[r], x, y);
                float v = x * x + y * y;
                v += __shfl_xor_sync(0xffffffffu, v, 16);
                v += __shfl_xor_sync(0xffffffffu, v, 8);
                v += __shfl_xor_sync(0xffffffffu, v, 4);
                v += __shfl_xor_sync(0xffffffffu, v, 2);
                v += __shfl_xor_sync(0xffffffffu, v, 1);
                if ((j & 31) == 0) s_red[(j >> 5) * TTC + r] = v;
            }
        }
        __syncthreads();
        if (j < TTC) {
            float s = 0.f;
            #pragma unroll
            for (int w = 0; w < 4; w++) s += s_red[w * TTC + j];
            float inv = rsqrtf(s);
            inv = inv * (1.5f - 0.5f * s * inv * inv);  // Newton step
            s_rsq[j] = inv;
        }
        __syncthreads();
        if (g2 == 0) {
            #pragma unroll
            for (int r = 0; r < TTC; r++) {
                int t = t0 + r;
                if (t < TOUT) {
                    float m = (t < L - 2) ? s_rsq[r] : 0.f;
                    float x, y; unpack2(acc2[r], x, y);
                    float2 o = make_float2(x * m, y * m);
                    *reinterpret_cast<float2*>(&outV[((size_t)b * TOUT + t) * HID + c2]) = o;
                }
            }
        }
    } else {
        // fully masked tile: fv rows exactly zero
        for (int idx = j; idx < TTC * 128; idx += 256) {
            int r = idx >> 7, cc = idx & 127;
            int t = t0 + r;
            if (t < TOUT)
                *reinterpret_cast<u64*>(&outV[((size_t)b * TOUT + t) * HID + 2 * cc]) = 0ull;
        }
    }
}

// ---------------------------------------------------------------------------
extern "C" void kernel_launch(void* const* d_in, const int* in_sizes, int n_in,
                              void* d_out, int out_size)
{
    (void)in_sizes; (void)n_in; (void)out_size;
    const int*   code    = (const int*)  d_in[0];
    const float* others  = (const float*)d_in[1];
    const int*   length  = (const int*)  d_in[2];
    const int*   target  = (const int*)  d_in[3];
    const int*   widx    = (const int*)  d_in[4];
    const float* Wf      = (const float*)d_in[5];
    const float* bf      = (const float*)d_in[6];
    const float* Wb      = (const float*)d_in[7];
    const float* bb      = (const float*)d_in[8];
    const float* W0      = (const float*)d_in[9];
    const float* b0      = (const float*)d_in[10];
    const float* W1      = (const float*)d_in[11];
    const float* b1      = (const float*)d_in[12];

    float* outF = (float*)d_out;
    float* outB = outF + (size_t)BB * TOUT * HID;
    float* outV = outB + (size_t)BB * TOUT * HID;

    tgt_kernel<<<BB, 256>>>(target, widx, Wf, Wb);
    kernelA<<<dim3(NTA, BB), 256>>>(code, others, length,
                                    Wf, bf, Wb, bb, W0, b0, outF, outB);
    kernelC<<<dim3(NTC, BB), 256>>>(length, W1, b1, outV);
}